// round 5
// baseline (speedup 1.0000x reference)
#include <cuda_runtime.h>
#include <math.h>

#define N_PIX 9216
#define C_DIM 64
#define H_DIM 96
#define W_DIM 96
#define BM 64
#define BN 64
#define NTILES (N_PIX / BN)   // 144

// Scratch (no cudaMalloc allowed): conv outputs in natural (C, HW) layout.
__device__ float g_y[C_DIM * N_PIX];   // dilated-conv output (q/k source)
__device__ float g_v[C_DIM * N_PIX];   // 1x1-conv output (v source)

// ---------------------------------------------------------------------------
// Dilated 3x3 conv, dilation=2, pad=2 (same-size). One CTA per output row h.
// Stages the 3 needed input rows (h-2, h, h+2) for all 64 in-channels in smem,
// zero-padded in w. Thread = (c_out pair, w slot of 12).
// ---------------------------------------------------------------------------
__global__ void dconv_kernel(const float* __restrict__ x,
                             const float* __restrict__ dW,
                             const float* __restrict__ db) {
    extern __shared__ float xs[];          // [3][64][100]  (w padded by 2 each side)
    const int ROWW = 100;
    int h = blockIdx.x;
    int tid = threadIdx.x;                 // 256 threads

    for (int i = tid; i < 3 * 64 * ROWW; i += 256) xs[i] = 0.f;
    __syncthreads();
    for (int i = tid; i < 3 * 64 * 96; i += 256) {
        int r   = i / (64 * 96);
        int rem = i % (64 * 96);
        int ci  = rem / 96;
        int w   = rem % 96;
        int hh  = h + 2 * (r - 1);
        if (hh >= 0 && hh < 96)
            xs[(r * 64 + ci) * ROWW + w + 2] = x[ci * N_PIX + hh * 96 + w];
    }
    __syncthreads();

    int cpair = tid / 8;                   // 0..31 -> c_out = 2*cpair, 2*cpair+1
    int wslot = tid % 8;                   // 12 contiguous w each
    int w0 = wslot * 12;
    int c0 = cpair * 2;

    float acc0[12], acc1[12];
    float b0 = db[c0], b1 = db[c0 + 1];
#pragma unroll
    for (int k = 0; k < 12; k++) { acc0[k] = b0; acc1[k] = b1; }

    for (int ci = 0; ci < 64; ci++) {
#pragma unroll
        for (int r = 0; r < 3; r++) {
#pragma unroll
            for (int kw = 0; kw < 3; kw++) {
                float wg0 = __ldg(&dW[ c0      * 576 + ci * 9 + r * 3 + kw]);
                float wg1 = __ldg(&dW[(c0 + 1) * 576 + ci * 9 + r * 3 + kw]);
                // x index: w + 2*(kw-1), stored at offset +2 -> w0 + k + 2*kw
                const float* xp = &xs[(r * 64 + ci) * ROWW + w0 + 2 * kw];
#pragma unroll
                for (int k = 0; k < 12; k++) {
                    float xv = xp[k];
                    acc0[k] += xv * wg0;
                    acc1[k] += xv * wg1;
                }
            }
        }
    }
#pragma unroll
    for (int k = 0; k < 12; k++) {
        g_y[ c0      * N_PIX + h * 96 + w0 + k] = acc0[k];
        g_y[(c0 + 1) * N_PIX + h * 96 + w0 + k] = acc1[k];
    }
}

// ---------------------------------------------------------------------------
// 1x1 conv: v[c][p] = cb[c] + sum_ci cW[c][ci] * x[ci][p]
// ---------------------------------------------------------------------------
__global__ void conv1x1_kernel(const float* __restrict__ x,
                               const float* __restrict__ cW,
                               const float* __restrict__ cb) {
    __shared__ float ws[64 * 64];
    int tid = threadIdx.x;                 // 128 threads
    for (int i = tid; i < 4096; i += 128) ws[i] = cW[i];
    __syncthreads();
    int p = blockIdx.x * 128 + tid;
#pragma unroll 1
    for (int chunk = 0; chunk < 4; chunk++) {
        float acc[16];
#pragma unroll
        for (int j = 0; j < 16; j++) acc[j] = __ldg(&cb[chunk * 16 + j]);
        for (int ci = 0; ci < 64; ci++) {
            float xv = x[ci * N_PIX + p];
#pragma unroll
            for (int j = 0; j < 16; j++)
                acc[j] += xv * ws[(chunk * 16 + j) * 64 + ci];
        }
#pragma unroll
        for (int j = 0; j < 16; j++)
            g_v[(chunk * 16 + j) * N_PIX + p] = acc[j];
    }
}

// ---------------------------------------------------------------------------
// Flash attention with threshold mask, fp32.
//   q[n][c] = g_y[n*64 + c]   (raw reshape view)
//   k[c][m] = g_y[c*9216 + m] (natural layout)
//   v[m][c] = g_v[m*64 + c]   (raw reshape view)
//   S = qk, thresholded (|s|>0.3 ? s : 0), online softmax over m, O = P@V.
//   out[c][n] = x[c][n] + O[n][c] / l[n]
// 256 threads as 16x16, each owns a 4x4 microtile.
// ---------------------------------------------------------------------------
__global__ void __launch_bounds__(256, 1)
attn_kernel(const float* __restrict__ x, float* __restrict__ out) {
    extern __shared__ float smem[];
    float* Qs = smem;                // [64][68]  Qs[c][n]  (transposed)
    float* Ks = Qs + 64 * 68;        // [64][68]  Ks[c][m]
    float* Ps = Ks + 64 * 68;        // [64][68]  Ps[n][m]
    float* Vs = Ps + 64 * 68;        // [64][68]  Vs[m][c]

    int tid = threadIdx.x;
    int tx = tid % 16, ty = tid / 16;
    int n0 = blockIdx.x * BM;

    // Load Q tile transposed: Qs[c][n] = g_y[(n0+n)*64 + c]
    for (int i = tid; i < 64 * 16; i += 256) {
        int n  = i / 16;
        int cq = (i % 16) * 4;
        float4 q = *reinterpret_cast<const float4*>(&g_y[(n0 + n) * 64 + cq]);
        Qs[(cq + 0) * 68 + n] = q.x;
        Qs[(cq + 1) * 68 + n] = q.y;
        Qs[(cq + 2) * 68 + n] = q.z;
        Qs[(cq + 3) * 68 + n] = q.w;
    }

    float O[4][4];
    float mrow[4], lrow[4];
#pragma unroll
    for (int i = 0; i < 4; i++) {
        mrow[i] = -1e30f; lrow[i] = 0.f;
#pragma unroll
        for (int j = 0; j < 4; j++) O[i][j] = 0.f;
    }
    __syncthreads();

    for (int t = 0; t < NTILES; t++) {
        int m0 = t * BN;
        // Load K tile (c-major, m contiguous) and V tile (m-major, c contiguous)
        for (int i = tid; i < 64 * 16; i += 256) {
            int row = i / 16;
            int q4  = (i % 16) * 4;
            float4 kv = *reinterpret_cast<const float4*>(&g_y[row * N_PIX + m0 + q4]);
            *reinterpret_cast<float4*>(&Ks[row * 68 + q4]) = kv;
            float4 vv = *reinterpret_cast<const float4*>(&g_v[(m0 + row) * 64 + q4]);
            *reinterpret_cast<float4*>(&Vs[row * 68 + q4]) = vv;
        }
        __syncthreads();

        // S microtile: s[i][j] = sum_c Qs[c][ty*4+i] * Ks[c][tx*4+j]
        float s[4][4];
#pragma unroll
        for (int i = 0; i < 4; i++)
#pragma unroll
            for (int j = 0; j < 4; j++) s[i][j] = 0.f;
#pragma unroll 8
        for (int c = 0; c < 64; c++) {
            float4 qv = *reinterpret_cast<const float4*>(&Qs[c * 68 + ty * 4]);
            float4 kv = *reinterpret_cast<const float4*>(&Ks[c * 68 + tx * 4]);
            float qa[4] = {qv.x, qv.y, qv.z, qv.w};
            float ka[4] = {kv.x, kv.y, kv.z, kv.w};
#pragma unroll
            for (int i = 0; i < 4; i++)
#pragma unroll
                for (int j = 0; j < 4; j++)
                    s[i][j] += qa[i] * ka[j];
        }

        // Threshold + per-row max (zeros participate in softmax!)
        float tmax[4];
#pragma unroll
        for (int i = 0; i < 4; i++) {
            float mx = -1e30f;
#pragma unroll
            for (int j = 0; j < 4; j++) {
                float v = s[i][j];
                v = (fabsf(v) > 0.3f) ? v : 0.f;
                s[i][j] = v;
                mx = fmaxf(mx, v);
            }
            tmax[i] = mx;
        }
#pragma unroll
        for (int off = 8; off >= 1; off >>= 1)
#pragma unroll
            for (int i = 0; i < 4; i++)
                tmax[i] = fmaxf(tmax[i], __shfl_xor_sync(0xffffffffu, tmax[i], off, 16));

        // Online softmax update
        float tsum[4];
#pragma unroll
        for (int i = 0; i < 4; i++) {
            float newm = fmaxf(mrow[i], tmax[i]);
            float corr = __expf(mrow[i] - newm);
            mrow[i] = newm;
            float sum = 0.f;
#pragma unroll
            for (int j = 0; j < 4; j++) {
                float p = __expf(s[i][j] - newm);
                s[i][j] = p;
                sum += p;
            }
            tsum[i] = sum;
            lrow[i] *= corr;
#pragma unroll
            for (int j = 0; j < 4; j++) O[i][j] *= corr;
        }
#pragma unroll
        for (int off = 8; off >= 1; off >>= 1)
#pragma unroll
            for (int i = 0; i < 4; i++)
                tsum[i] += __shfl_xor_sync(0xffffffffu, tsum[i], off, 16);
#pragma unroll
        for (int i = 0; i < 4; i++) lrow[i] += tsum[i];

        // Stage P row-major (float4 stores, no bank conflicts)
#pragma unroll
        for (int i = 0; i < 4; i++)
            *reinterpret_cast<float4*>(&Ps[(ty * 4 + i) * 68 + tx * 4]) =
                make_float4(s[i][0], s[i][1], s[i][2], s[i][3]);
        __syncthreads();

        // O += P @ V : O[i][j] += sum_m Ps[ty*4+i][m] * Vs[m][tx*4+j]
#pragma unroll 2
        for (int m = 0; m < 64; m += 4) {
            float4 pv[4], vv[4];
#pragma unroll
            for (int i = 0; i < 4; i++)
                pv[i] = *reinterpret_cast<const float4*>(&Ps[(ty * 4 + i) * 68 + m]);
#pragma unroll
            for (int r = 0; r < 4; r++)
                vv[r] = *reinterpret_cast<const float4*>(&Vs[(m + r) * 68 + tx * 4]);
#pragma unroll
            for (int i = 0; i < 4; i++) {
                float pa[4] = {pv[i].x, pv[i].y, pv[i].z, pv[i].w};
#pragma unroll
                for (int r = 0; r < 4; r++) {
                    O[i][0] += pa[r] * vv[r].x;
                    O[i][1] += pa[r] * vv[r].y;
                    O[i][2] += pa[r] * vv[r].z;
                    O[i][3] += pa[r] * vv[r].w;
                }
            }
        }
        __syncthreads();   // protect Ks/Vs/Ps before next tile's loads
    }

    // Epilogue: out[c][n] = x[c][n] + O[n][c]/l   (transposed scatter)
#pragma unroll
    for (int i = 0; i < 4; i++) {
        float inv = 1.f / lrow[i];
        int n = n0 + ty * 4 + i;
#pragma unroll
        for (int j = 0; j < 4; j++) {
            int c = tx * 4 + j;
            int idx = c * N_PIX + n;
            out[idx] = x[idx] + O[i][j] * inv;
        }
    }
}

// ---------------------------------------------------------------------------
extern "C" void kernel_launch(void* const* d_in, const int* in_sizes, int n_in,
                              void* d_out, int out_size) {
    const float* x  = (const float*)d_in[0];
    const float* dW = (const float*)d_in[1];
    const float* db = (const float*)d_in[2];
    const float* cW = (const float*)d_in[3];
    const float* cb = (const float*)d_in[4];
    float* out = (float*)d_out;

    // Idempotent, capture-safe (host attribute set, not a stream op).
    cudaFuncSetAttribute(dconv_kernel, cudaFuncAttributeMaxDynamicSharedMemorySize, 76800);
    cudaFuncSetAttribute(attn_kernel,  cudaFuncAttributeMaxDynamicSharedMemorySize, 69632);

    dconv_kernel<<<96, 256, 76800>>>(x, dW, db);
    conv1x1_kernel<<<72, 128>>>(x, cW, cb);
    attn_kernel<<<144, 256, 69632>>>(x, out);
}

// round 6
// speedup vs baseline: 1.0018x; 1.0018x over previous
#include <cuda_runtime.h>
#include <math.h>

#define N_PIX 9216
#define C_DIM 64
#define H_DIM 96
#define W_DIM 96
#define BM 64
#define BN 64
#define NTILES (N_PIX / BN)   // 144

// Scratch (no cudaMalloc allowed): conv outputs in natural (C, HW) layout.
__device__ float g_y[C_DIM * N_PIX];   // dilated-conv output (q/k source)
__device__ float g_v[C_DIM * N_PIX];   // 1x1-conv output (v source)

// ---------------------------------------------------------------------------
// Dilated 3x3 conv, dilation=2, pad=2 (same-size). One CTA per output row h.
// Stages the 3 needed input rows (h-2, h, h+2) for all 64 in-channels in smem,
// zero-padded in w. Thread = (c_out pair, w slot of 12).
// ---------------------------------------------------------------------------
__global__ void dconv_kernel(const float* __restrict__ x,
                             const float* __restrict__ dW,
                             const float* __restrict__ db) {
    extern __shared__ float xs[];          // [3][64][100]  (w padded by 2 each side)
    const int ROWW = 100;
    int h = blockIdx.x;
    int tid = threadIdx.x;                 // 256 threads

    for (int i = tid; i < 3 * 64 * ROWW; i += 256) xs[i] = 0.f;
    __syncthreads();
    for (int i = tid; i < 3 * 64 * 96; i += 256) {
        int r   = i / (64 * 96);
        int rem = i % (64 * 96);
        int ci  = rem / 96;
        int w   = rem % 96;
        int hh  = h + 2 * (r - 1);
        if (hh >= 0 && hh < 96)
            xs[(r * 64 + ci) * ROWW + w + 2] = x[ci * N_PIX + hh * 96 + w];
    }
    __syncthreads();

    int cpair = tid / 8;                   // 0..31 -> c_out = 2*cpair, 2*cpair+1
    int wslot = tid % 8;                   // 12 contiguous w each
    int w0 = wslot * 12;
    int c0 = cpair * 2;

    float acc0[12], acc1[12];
    float b0 = db[c0], b1 = db[c0 + 1];
#pragma unroll
    for (int k = 0; k < 12; k++) { acc0[k] = b0; acc1[k] = b1; }

    for (int ci = 0; ci < 64; ci++) {
#pragma unroll
        for (int r = 0; r < 3; r++) {
#pragma unroll
            for (int kw = 0; kw < 3; kw++) {
                float wg0 = __ldg(&dW[ c0      * 576 + ci * 9 + r * 3 + kw]);
                float wg1 = __ldg(&dW[(c0 + 1) * 576 + ci * 9 + r * 3 + kw]);
                // x index: w + 2*(kw-1), stored at offset +2 -> w0 + k + 2*kw
                const float* xp = &xs[(r * 64 + ci) * ROWW + w0 + 2 * kw];
#pragma unroll
                for (int k = 0; k < 12; k++) {
                    float xv = xp[k];
                    acc0[k] += xv * wg0;
                    acc1[k] += xv * wg1;
                }
            }
        }
    }
#pragma unroll
    for (int k = 0; k < 12; k++) {
        g_y[ c0      * N_PIX + h * 96 + w0 + k] = acc0[k];
        g_y[(c0 + 1) * N_PIX + h * 96 + w0 + k] = acc1[k];
    }
}

// ---------------------------------------------------------------------------
// 1x1 conv: v[c][p] = cb[c] + sum_ci cW[c][ci] * x[ci][p]
// ---------------------------------------------------------------------------
__global__ void conv1x1_kernel(const float* __restrict__ x,
                               const float* __restrict__ cW,
                               const float* __restrict__ cb) {
    __shared__ float ws[64 * 64];
    int tid = threadIdx.x;                 // 128 threads
    for (int i = tid; i < 4096; i += 128) ws[i] = cW[i];
    __syncthreads();
    int p = blockIdx.x * 128 + tid;
#pragma unroll 1
    for (int chunk = 0; chunk < 4; chunk++) {
        float acc[16];
#pragma unroll
        for (int j = 0; j < 16; j++) acc[j] = __ldg(&cb[chunk * 16 + j]);
        for (int ci = 0; ci < 64; ci++) {
            float xv = x[ci * N_PIX + p];
#pragma unroll
            for (int j = 0; j < 16; j++)
                acc[j] += xv * ws[(chunk * 16 + j) * 64 + ci];
        }
#pragma unroll
        for (int j = 0; j < 16; j++)
            g_v[(chunk * 16 + j) * N_PIX + p] = acc[j];
    }
}

// ---------------------------------------------------------------------------
// Flash attention with threshold mask, fp32.
//   q[n][c] = g_y[n*64 + c]   (raw reshape view)
//   k[c][m] = g_y[c*9216 + m] (natural layout)
//   v[m][c] = g_v[m*64 + c]   (raw reshape view)
//   S = qk, thresholded (|s|>0.3 ? s : 0), online softmax over m, O = P@V.
//   out[c][n] = x[c][n] + O[n][c] / l[n]
// 256 threads as 16x16, each owns a 4x4 microtile.
// ---------------------------------------------------------------------------
__global__ void __launch_bounds__(256, 1)
attn_kernel(const float* __restrict__ x, float* __restrict__ out) {
    extern __shared__ float smem[];
    float* Qs = smem;                // [64][68]  Qs[c][n]  (transposed)
    float* Ks = Qs + 64 * 68;        // [64][68]  Ks[c][m]
    float* Ps = Ks + 64 * 68;        // [64][68]  Ps[n][m]
    float* Vs = Ps + 64 * 68;        // [64][68]  Vs[m][c]

    int tid = threadIdx.x;
    int tx = tid % 16, ty = tid / 16;
    int n0 = blockIdx.x * BM;

    // Load Q tile transposed: Qs[c][n] = g_y[(n0+n)*64 + c]
    for (int i = tid; i < 64 * 16; i += 256) {
        int n  = i / 16;
        int cq = (i % 16) * 4;
        float4 q = *reinterpret_cast<const float4*>(&g_y[(n0 + n) * 64 + cq]);
        Qs[(cq + 0) * 68 + n] = q.x;
        Qs[(cq + 1) * 68 + n] = q.y;
        Qs[(cq + 2) * 68 + n] = q.z;
        Qs[(cq + 3) * 68 + n] = q.w;
    }

    float O[4][4];
    float mrow[4], lrow[4];
#pragma unroll
    for (int i = 0; i < 4; i++) {
        mrow[i] = -1e30f; lrow[i] = 0.f;
#pragma unroll
        for (int j = 0; j < 4; j++) O[i][j] = 0.f;
    }
    __syncthreads();

    for (int t = 0; t < NTILES; t++) {
        int m0 = t * BN;
        // Load K tile (c-major, m contiguous) and V tile (m-major, c contiguous)
        for (int i = tid; i < 64 * 16; i += 256) {
            int row = i / 16;
            int q4  = (i % 16) * 4;
            float4 kv = *reinterpret_cast<const float4*>(&g_y[row * N_PIX + m0 + q4]);
            *reinterpret_cast<float4*>(&Ks[row * 68 + q4]) = kv;
            float4 vv = *reinterpret_cast<const float4*>(&g_v[(m0 + row) * 64 + q4]);
            *reinterpret_cast<float4*>(&Vs[row * 68 + q4]) = vv;
        }
        __syncthreads();

        // S microtile: s[i][j] = sum_c Qs[c][ty*4+i] * Ks[c][tx*4+j]
        float s[4][4];
#pragma unroll
        for (int i = 0; i < 4; i++)
#pragma unroll
            for (int j = 0; j < 4; j++) s[i][j] = 0.f;
#pragma unroll 8
        for (int c = 0; c < 64; c++) {
            float4 qv = *reinterpret_cast<const float4*>(&Qs[c * 68 + ty * 4]);
            float4 kv = *reinterpret_cast<const float4*>(&Ks[c * 68 + tx * 4]);
            float qa[4] = {qv.x, qv.y, qv.z, qv.w};
            float ka[4] = {kv.x, kv.y, kv.z, kv.w};
#pragma unroll
            for (int i = 0; i < 4; i++)
#pragma unroll
                for (int j = 0; j < 4; j++)
                    s[i][j] += qa[i] * ka[j];
        }

        // Threshold + per-row max (zeros participate in softmax!)
        float tmax[4];
#pragma unroll
        for (int i = 0; i < 4; i++) {
            float mx = -1e30f;
#pragma unroll
            for (int j = 0; j < 4; j++) {
                float v = s[i][j];
                v = (fabsf(v) > 0.3f) ? v : 0.f;
                s[i][j] = v;
                mx = fmaxf(mx, v);
            }
            tmax[i] = mx;
        }
#pragma unroll
        for (int off = 8; off >= 1; off >>= 1)
#pragma unroll
            for (int i = 0; i < 4; i++)
                tmax[i] = fmaxf(tmax[i], __shfl_xor_sync(0xffffffffu, tmax[i], off, 16));

        // Online softmax update
        float tsum[4];
#pragma unroll
        for (int i = 0; i < 4; i++) {
            float newm = fmaxf(mrow[i], tmax[i]);
            float corr = __expf(mrow[i] - newm);
            mrow[i] = newm;
            float sum = 0.f;
#pragma unroll
            for (int j = 0; j < 4; j++) {
                float p = __expf(s[i][j] - newm);
                s[i][j] = p;
                sum += p;
            }
            tsum[i] = sum;
            lrow[i] *= corr;
#pragma unroll
            for (int j = 0; j < 4; j++) O[i][j] *= corr;
        }
#pragma unroll
        for (int off = 8; off >= 1; off >>= 1)
#pragma unroll
            for (int i = 0; i < 4; i++)
                tsum[i] += __shfl_xor_sync(0xffffffffu, tsum[i], off, 16);
#pragma unroll
        for (int i = 0; i < 4; i++) lrow[i] += tsum[i];

        // Stage P row-major (float4 stores, no bank conflicts)
#pragma unroll
        for (int i = 0; i < 4; i++)
            *reinterpret_cast<float4*>(&Ps[(ty * 4 + i) * 68 + tx * 4]) =
                make_float4(s[i][0], s[i][1], s[i][2], s[i][3]);
        __syncthreads();

        // O += P @ V : O[i][j] += sum_m Ps[ty*4+i][m] * Vs[m][tx*4+j]
#pragma unroll 2
        for (int m = 0; m < 64; m += 4) {
            float4 pv[4], vv[4];
#pragma unroll
            for (int i = 0; i < 4; i++)
                pv[i] = *reinterpret_cast<const float4*>(&Ps[(ty * 4 + i) * 68 + m]);
#pragma unroll
            for (int r = 0; r < 4; r++)
                vv[r] = *reinterpret_cast<const float4*>(&Vs[(m + r) * 68 + tx * 4]);
#pragma unroll
            for (int i = 0; i < 4; i++) {
                float pa[4] = {pv[i].x, pv[i].y, pv[i].z, pv[i].w};
#pragma unroll
                for (int r = 0; r < 4; r++) {
                    O[i][0] += pa[r] * vv[r].x;
                    O[i][1] += pa[r] * vv[r].y;
                    O[i][2] += pa[r] * vv[r].z;
                    O[i][3] += pa[r] * vv[r].w;
                }
            }
        }
        __syncthreads();   // protect Ks/Vs/Ps before next tile's loads
    }

    // Epilogue: out[c][n] = x[c][n] + O[n][c]/l   (transposed scatter)
#pragma unroll
    for (int i = 0; i < 4; i++) {
        float inv = 1.f / lrow[i];
        int n = n0 + ty * 4 + i;
#pragma unroll
        for (int j = 0; j < 4; j++) {
            int c = tx * 4 + j;
            int idx = c * N_PIX + n;
            out[idx] = x[idx] + O[i][j] * inv;
        }
    }
}

// ---------------------------------------------------------------------------
extern "C" void kernel_launch(void* const* d_in, const int* in_sizes, int n_in,
                              void* d_out, int out_size) {
    const float* x  = (const float*)d_in[0];
    const float* dW = (const float*)d_in[1];
    const float* db = (const float*)d_in[2];
    const float* cW = (const float*)d_in[3];
    const float* cb = (const float*)d_in[4];
    float* out = (float*)d_out;

    // Idempotent, capture-safe (host attribute set, not a stream op).
    cudaFuncSetAttribute(dconv_kernel, cudaFuncAttributeMaxDynamicSharedMemorySize, 76800);
    cudaFuncSetAttribute(attn_kernel,  cudaFuncAttributeMaxDynamicSharedMemorySize, 69632);

    dconv_kernel<<<96, 256, 76800>>>(x, dW, db);
    conv1x1_kernel<<<72, 128>>>(x, cW, cb);
    attn_kernel<<<144, 256, 69632>>>(x, out);
}